// round 1
// baseline (speedup 1.0000x reference)
#include <cuda_runtime.h>
#include <math.h>

#define HIDDEN 128
#define NGRAPH 4096
#define POOL_DIM (3 * HIDDEN)

// Scratch for pooled features [NGRAPH, 3*HIDDEN] = 6 MB (device global: no allocs allowed)
__device__ float g_pooled[NGRAPH * POOL_DIM];

// ---------------------------------------------------------------------------
// Phase A: one block per graph. batch is SORTED, so each graph's rows are a
// contiguous range found by binary search. 512 threads = 4 row-groups x 128
// channels. Single pass computes sum & max; count = end - start (free).
// ---------------------------------------------------------------------------
__device__ __forceinline__ int batch_val(const int* __restrict__ w, int i, bool is64) {
    // graph ids are small nonnegative -> low 32-bit word suffices for int64
    return is64 ? w[2 * i] : w[i];
}

__global__ void __launch_bounds__(512, 4)
pool_kernel(const float* __restrict__ x, const int* __restrict__ batch_raw, int n_nodes) {
    const int g = blockIdx.x;
    __shared__ int s_range[2];

    // int64 vs int32 detection (little-endian): for int64 data with n even,
    // word[n-1] is a high half (0) while word[n-2] is a nonzero low half.
    const bool is64 = (batch_raw[n_nodes - 1] == 0) && (batch_raw[n_nodes - 2] != 0);

    if (threadIdx.x == 0) {
        int lo = 0, hi = n_nodes;
        while (lo < hi) { int mid = (lo + hi) >> 1;
            if (batch_val(batch_raw, mid, is64) < g) lo = mid + 1; else hi = mid; }
        s_range[0] = lo;
    }
    if (threadIdx.x == 32) {
        int lo = 0, hi = n_nodes;
        while (lo < hi) { int mid = (lo + hi) >> 1;
            if (batch_val(batch_raw, mid, is64) < g + 1) lo = mid + 1; else hi = mid; }
        s_range[1] = lo;
    }
    __syncthreads();
    const int start = s_range[0];
    const int end   = s_range[1];

    const int c = threadIdx.x & (HIDDEN - 1);   // channel
    const int h = threadIdx.x >> 7;             // row group 0..3

    float s0 = 0.f, s1 = 0.f;
    float m0 = -3.402823466e38f, m1 = -3.402823466e38f;

    int i = start + h;
    // stride-4 across row groups, manual 2x unroll -> MLP 8 per thread
    for (; i + 4 < end; i += 8) {
        float v0 = x[(size_t)i * HIDDEN + c];
        float v1 = x[(size_t)(i + 4) * HIDDEN + c];
        s0 += v0; m0 = fmaxf(m0, v0);
        s1 += v1; m1 = fmaxf(m1, v1);
    }
    if (i < end) {
        float v = x[(size_t)i * HIDDEN + c];
        s0 += v; m0 = fmaxf(m0, v);
    }
    float sum = s0 + s1;
    float mx  = fmaxf(m0, m1);

    __shared__ float s_sum[4][HIDDEN];
    __shared__ float s_max[4][HIDDEN];
    s_sum[h][c] = sum;
    s_max[h][c] = mx;
    __syncthreads();

    if (h == 0) {
        float S = s_sum[0][c] + s_sum[1][c] + s_sum[2][c] + s_sum[3][c];
        float M = fmaxf(fmaxf(s_max[0][c], s_max[1][c]), fmaxf(s_max[2][c], s_max[3][c]));
        int cnt = end - start;
        float mean = S / fmaxf((float)cnt, 1.0f);     // ref: sums / max(counts,1)
        float mout = (cnt > 0) ? M : 0.0f;            // ref: where(counts>0, maxs, 0)
        float* o = g_pooled + (size_t)g * POOL_DIM;
        o[c]              = mean;
        o[HIDDEN + c]     = mout;
        o[2 * HIDDEN + c] = S;
    }
}

// ---------------------------------------------------------------------------
// Phase B: fused GEMM [4096,384]x[384,128] + bias + LayerNorm + exact GELU.
// 128 blocks x 256 threads; each block does 32 graph rows. W tile and a
// TRANSPOSED pooled tile live in smem so the inner loop is 4xLDS.128
// (broadcast) + 1 LDS + 16 FMA per k. W read from L2 once per block
// (128 x 192KB = 25 MB of L2 traffic, ~2 us) instead of once per graph.
// ---------------------------------------------------------------------------
__global__ void __launch_bounds__(256, 4)
gemm_ln_gelu_kernel(const float* __restrict__ W, const float* __restrict__ bias,
                    const float* __restrict__ gamma, const float* __restrict__ beta,
                    float* __restrict__ out) {
    const int GT = 32;   // graph rows per block
    const int KT = 64;   // k tile

    __shared__ float sW[KT][HIDDEN];      // 32 KB
    __shared__ float sP[KT][GT + 4];      // transposed pooled tile, stride 36 (16B-aligned)
    __shared__ float sH[GT][HIDDEN + 4];  // post-GEMM h for LN

    const int g0 = blockIdx.x * GT;
    const int j  = threadIdx.x & (HIDDEN - 1);  // output column
    const int rg = threadIdx.x >> 7;            // 0/1: rows [rg*16, rg*16+16)

    float acc[16];
#pragma unroll
    for (int r = 0; r < 16; r++) acc[r] = 0.f;

    for (int kt = 0; kt < POOL_DIM; kt += KT) {
        __syncthreads();
        // W tile: coalesced
        for (int idx = threadIdx.x; idx < KT * HIDDEN; idx += 256) {
            int kk = idx >> 7, col = idx & (HIDDEN - 1);
            sW[kk][col] = W[(size_t)(kt + kk) * HIDDEN + col];
        }
        // pooled tile, transposed into smem (global read coalesced along k)
        for (int idx = threadIdx.x; idx < GT * KT; idx += 256) {
            int r = idx / KT, kk = idx - r * KT;
            sP[kk][r] = g_pooled[(size_t)(g0 + r) * POOL_DIM + kt + kk];
        }
        __syncthreads();

#pragma unroll 4
        for (int kk = 0; kk < KT; kk++) {
            float w = sW[kk][j];
            const float4* p4 = (const float4*)&sP[kk][rg * 16];
            float4 a0 = p4[0], a1 = p4[1], a2 = p4[2], a3 = p4[3];
            acc[0]  += a0.x * w;  acc[1]  += a0.y * w;
            acc[2]  += a0.z * w;  acc[3]  += a0.w * w;
            acc[4]  += a1.x * w;  acc[5]  += a1.y * w;
            acc[6]  += a1.z * w;  acc[7]  += a1.w * w;
            acc[8]  += a2.x * w;  acc[9]  += a2.y * w;
            acc[10] += a2.z * w;  acc[11] += a2.w * w;
            acc[12] += a3.x * w;  acc[13] += a3.y * w;
            acc[14] += a3.z * w;  acc[15] += a3.w * w;
        }
    }

    float bj = bias[j];
#pragma unroll
    for (int r = 0; r < 16; r++) sH[rg * 16 + r][j] = acc[r] + bj;
    __syncthreads();

    // LayerNorm + exact GELU: 8 warps, 4 rows each; lane covers 4 columns
    const int warp = threadIdx.x >> 5, lane = threadIdx.x & 31;
    for (int row = warp; row < GT; row += 8) {
        float v[4];
#pragma unroll
        for (int q = 0; q < 4; q++) v[q] = sH[row][lane + 32 * q];

        float s = v[0] + v[1] + v[2] + v[3];
#pragma unroll
        for (int o = 16; o > 0; o >>= 1) s += __shfl_xor_sync(0xffffffffu, s, o);
        float mu = s * (1.0f / 128.0f);

        float vs = 0.f;
#pragma unroll
        for (int q = 0; q < 4; q++) { float d = v[q] - mu; vs += d * d; }
#pragma unroll
        for (int o = 16; o > 0; o >>= 1) vs += __shfl_xor_sync(0xffffffffu, vs, o);
        float inv = rsqrtf(vs * (1.0f / 128.0f) + 1e-5f);

#pragma unroll
        for (int q = 0; q < 4; q++) {
            int col = lane + 32 * q;
            float y = (v[q] - mu) * inv * gamma[col] + beta[col];
            float ge = 0.5f * y * (1.0f + erff(y * 0.70710678118654752f));
            out[(size_t)(g0 + row) * HIDDEN + col] = ge;
        }
    }
}

// ---------------------------------------------------------------------------
extern "C" void kernel_launch(void* const* d_in, const int* in_sizes, int n_in,
                              void* d_out, int out_size) {
    // Identify inputs by element count (robust to metadata ordering / the
    // scalar num_graphs input): x = largest; batch = n_nodes; W = 3*128*128;
    // then b, gamma, beta are the three size-128 vectors in declaration order.
    int ix = -1;
    long long maxsz = -1;
    for (int i = 0; i < n_in; i++)
        if ((long long)in_sizes[i] > maxsz) { maxsz = in_sizes[i]; ix = i; }
    const int n_nodes = (int)(maxsz / HIDDEN);

    int ib = -1, iw = -1, vecs[3] = {-1, -1, -1}; int nv = 0;
    for (int i = 0; i < n_in; i++) {
        if (i == ix) continue;
        if (in_sizes[i] == n_nodes) ib = i;
        else if (in_sizes[i] == POOL_DIM * HIDDEN) iw = i;
        else if (in_sizes[i] == HIDDEN && nv < 3) vecs[nv++] = i;
    }

    const float* x     = (const float*)d_in[ix];
    const int*   batch = (const int*)d_in[ib];   // width auto-detected in-kernel
    const float* W     = (const float*)d_in[iw];
    const float* b     = (const float*)d_in[vecs[0]];
    const float* gamma = (const float*)d_in[vecs[1]];
    const float* beta  = (const float*)d_in[vecs[2]];
    float* out = (float*)d_out;

    pool_kernel<<<NGRAPH, 512>>>(x, batch, n_nodes);
    gemm_ln_gelu_kernel<<<NGRAPH / 32, 256>>>(W, b, gamma, beta, out);
}